// round 3
// baseline (speedup 1.0000x reference)
#include <cuda_runtime.h>

// MultiHeadAttention_45732811768295 — fp32, f32x2 (FFMA2) GEMM cores.
//
// Pipeline (all on default stream, graph-capturable, no allocations):
//   1) qkv_proj_kernel : q/k/v = X @ W + b          (3x [16384,1024]x[1024,64])
//   2) weff_kernel     : W_eff[d,m] = sum_h Wo[h*64+d, m]   ([64,1024])
//   3) attn_kernel     : flash-style softmax(QK^T/8) V per batch
//   4) outproj_kernel  : out = ctx @ W_eff + bo     ([16384,64]x[64,1024])

#define B_  8
#define S_  2048
#define DM  1024
#define HD  64
#define ROWS_TOT (B_ * S_)   // 16384

typedef unsigned long long u64;

__device__ __forceinline__ u64 pack2(float x, float y) {
    u64 r; asm("mov.b64 %0, {%1,%2};" : "=l"(r) : "f"(x), "f"(y)); return r;
}
__device__ __forceinline__ u64 dup2(float x) { return pack2(x, x); }
__device__ __forceinline__ void fma2(u64 &d, u64 a, u64 b) {
    asm("fma.rn.f32x2 %0, %1, %2, %0;" : "+l"(d) : "l"(a), "l"(b));
}
__device__ __forceinline__ u64 mul2(u64 a, u64 b) {
    u64 d; asm("mul.rn.f32x2 %0, %1, %2;" : "=l"(d) : "l"(a), "l"(b)); return d;
}
__device__ __forceinline__ float2 unpk2(u64 v) {
    float2 f; asm("mov.b64 {%0,%1}, %2;" : "=f"(f.x), "=f"(f.y) : "l"(v)); return f;
}

// Scratch (device globals; no runtime allocation allowed)
__device__ float g_q[ROWS_TOT * HD];
__device__ float g_k[ROWS_TOT * HD];
__device__ float g_v[ROWS_TOT * HD];
__device__ float g_ctx[ROWS_TOT * HD];
__device__ float g_weff[HD * DM];

// ---------------------------------------------------------------------------
// 1) QKV projection: out[r,c] = sum_k X[r,k] * W[k,c] + b[c]
//    Block tile 128x64, Ktile=32, 256 threads, thread tile 8x4 (2 f32x2 pairs)
// ---------------------------------------------------------------------------
__global__ __launch_bounds__(256) void qkv_proj_kernel(
    const float* __restrict__ in_q, const float* __restrict__ in_k, const float* __restrict__ in_v,
    const float* __restrict__ Wq, const float* __restrict__ Wk, const float* __restrict__ Wv,
    const float* __restrict__ bq, const float* __restrict__ bk, const float* __restrict__ bv)
{
    __shared__ float As[128 * 32];   // [row][k]  (natural)
    __shared__ float Bs[32 * 64];    // [k][c]    (natural)

    const float* X; const float* W; const float* bias; float* out;
    if (blockIdx.z == 0)      { X = in_q; W = Wq; bias = bq; out = g_q; }
    else if (blockIdx.z == 1) { X = in_k; W = Wk; bias = bk; out = g_k; }
    else                      { X = in_v; W = Wv; bias = bv; out = g_v; }

    const int tid = threadIdx.x;
    const int ty  = tid >> 4;     // 0..15 -> rows ty*8..+7
    const int tx  = tid & 15;     // 0..15 -> cols tx*4..+3
    const int rowBase = blockIdx.x * 128;

    const float4* X4  = (const float4*)X;
    const float4* W4  = (const float4*)W;
    float4* As4 = (float4*)As;
    float4* Bs4 = (float4*)Bs;

    u64 acc[8][2];
#pragma unroll
    for (int i = 0; i < 8; i++) { acc[i][0] = 0ull; acc[i][1] = 0ull; }

    for (int kt = 0; kt < 32; kt++) {
        const int k0 = kt * 32;
#pragma unroll
        for (int l = 0; l < 4; l++) {                 // 128x32 = 1024 float4
            int idx4 = tid + l * 256;
            int r = idx4 >> 3, k4 = idx4 & 7;
            As4[idx4] = X4[(rowBase + r) * 256 + (k0 >> 2) + k4];
        }
#pragma unroll
        for (int l = 0; l < 2; l++) {                 // 32x64 = 512 float4
            int idx4 = tid + l * 256;
            int kr = idx4 >> 4, c4 = idx4 & 15;
            Bs4[idx4] = W4[(k0 + kr) * 16 + c4];
        }
        __syncthreads();

#pragma unroll
        for (int k4 = 0; k4 < 8; k4++) {
            float4 a4[8];
#pragma unroll
            for (int i = 0; i < 8; i++) a4[i] = As4[(ty * 8 + i) * 8 + k4];
#pragma unroll
            for (int e = 0; e < 4; e++) {
                float4 b = Bs4[(k4 * 4 + e) * 16 + tx];
                u64 b01 = pack2(b.x, b.y), b23 = pack2(b.z, b.w);
#pragma unroll
                for (int i = 0; i < 8; i++) {
                    float av = (e == 0) ? a4[i].x : (e == 1) ? a4[i].y : (e == 2) ? a4[i].z : a4[i].w;
                    u64 ad = dup2(av);
                    fma2(acc[i][0], ad, b01);
                    fma2(acc[i][1], ad, b23);
                }
            }
        }
        __syncthreads();
    }

    const float4 bb = ((const float4*)bias)[tx];
    float4* out4 = (float4*)out;
#pragma unroll
    for (int i = 0; i < 8; i++) {
        float2 p0 = unpk2(acc[i][0]);
        float2 p1 = unpk2(acc[i][1]);
        out4[(rowBase + ty * 8 + i) * 16 + tx] =
            make_float4(p0.x + bb.x, p0.y + bb.y, p1.x + bb.z, p1.y + bb.w);
    }
}

// ---------------------------------------------------------------------------
// 2) W_eff[d,m] = sum_h Wo[h*64+d, m]   (tile(ctx,16)@Wo == ctx@W_eff)
// ---------------------------------------------------------------------------
__global__ void weff_kernel(const float* __restrict__ Wo)
{
    int idx = blockIdx.x * 256 + threadIdx.x;     // 64*1024 = 65536
    int d = idx >> 10, m = idx & 1023;
    float s = 0.f;
#pragma unroll
    for (int h = 0; h < 16; h++) s += Wo[(h * 64 + d) * 1024 + m];
    g_weff[idx] = s;
    (void)d;
}

// ---------------------------------------------------------------------------
// 3) Attention: per (batch, 64-row q-tile) block, loop 64-key tiles,
//    online softmax, ctx accumulated in registers (f32x2 pairs).
//    Thread tile: 4 rows x 4 cols; shfl over tx-halves for row reductions.
// ---------------------------------------------------------------------------
#define ATTN_SMEM_FLOATS (64*64 + 64*68 + 64*64 + 64*68)
#define ATTN_SMEM_BYTES  (ATTN_SMEM_FLOATS * 4)

__global__ __launch_bounds__(256) void attn_kernel()
{
    extern __shared__ float sm[];
    float* Qs = sm;                 // [i][d]   64x64 natural
    float* Ks = Qs + 64 * 64;       // [d][j]   64x68 transposed (pad 4)
    float* Vs = Ks + 64 * 68;       // [j][d]   64x64 natural
    float* Ps = Vs + 64 * 64;       // [i][j]   64x68 (pad 4)

    const int b  = blockIdx.y;
    const int qt = blockIdx.x;
    const int tid = threadIdx.x;
    const int ty = tid >> 4;        // rows ty*4..+3
    const int tx = tid & 15;        // cols tx*4..+3

    const float4* Qg4 = (const float4*)(g_q + (b * S_ + qt * 64) * HD);
    const float*  Kg  = g_k + b * S_ * HD;
    const float*  Vg  = g_v + b * S_ * HD;

    float4* Qs4 = (float4*)Qs;
    float4* Ks4 = (float4*)Ks;      // row stride 17 float4
    float4* Vs4 = (float4*)Vs;
    float4* Ps4 = (float4*)Ps;      // row stride 17 float4

#pragma unroll
    for (int l = 0; l < 4; l++) { int idx4 = tid + l * 256; Qs4[idx4] = Qg4[idx4]; }

    float m_r[4], l_r[4];
    u64 o2[4][2];
#pragma unroll
    for (int ii = 0; ii < 4; ii++) { m_r[ii] = -1e30f; l_r[ii] = 0.f; o2[ii][0] = 0ull; o2[ii][1] = 0ull; }

    for (int kt = 0; kt < 32; kt++) {
        const float4* Kt4 = (const float4*)(Kg + kt * 64 * HD);
        const float4* Vt4 = (const float4*)(Vg + kt * 64 * HD);
#pragma unroll
        for (int l = 0; l < 4; l++) {
            int idx4 = tid + l * 256;           // 0..1023
            int d4 = idx4 >> 6, j = idx4 & 63;  // lanes: j consecutive -> conflict-free STS
            float4 v = Kt4[j * 16 + d4];
            int d = d4 * 4;
            Ks[(d + 0) * 68 + j] = v.x;
            Ks[(d + 1) * 68 + j] = v.y;
            Ks[(d + 2) * 68 + j] = v.z;
            Ks[(d + 3) * 68 + j] = v.w;
            Vs4[idx4] = Vt4[idx4];
        }
        __syncthreads();

        // S = Q K^T (contraction over d)
        u64 s2[4][2];
#pragma unroll
        for (int ii = 0; ii < 4; ii++) { s2[ii][0] = 0ull; s2[ii][1] = 0ull; }

#pragma unroll
        for (int d4 = 0; d4 < 16; d4++) {
            float4 a4[4];
#pragma unroll
            for (int ii = 0; ii < 4; ii++) a4[ii] = Qs4[(ty * 4 + ii) * 16 + d4];
#pragma unroll
            for (int e = 0; e < 4; e++) {
                float4 bk = Ks4[(d4 * 4 + e) * 17 + tx];
                u64 b01 = pack2(bk.x, bk.y), b23 = pack2(bk.z, bk.w);
#pragma unroll
                for (int ii = 0; ii < 4; ii++) {
                    float av = (e == 0) ? a4[ii].x : (e == 1) ? a4[ii].y : (e == 2) ? a4[ii].z : a4[ii].w;
                    u64 ad = dup2(av);
                    fma2(s2[ii][0], ad, b01);
                    fma2(s2[ii][1], ad, b23);
                }
            }
        }

        // Online softmax update (row reductions over the 16 tx lanes)
#pragma unroll
        for (int ii = 0; ii < 4; ii++) {
            float2 sa = unpk2(s2[ii][0]);
            float2 sb = unpk2(s2[ii][1]);
            float s0 = sa.x * 0.125f, s1 = sa.y * 0.125f, s2v = sb.x * 0.125f, s3 = sb.y * 0.125f;
            float tm = fmaxf(fmaxf(s0, s1), fmaxf(s2v, s3));
            tm = fmaxf(tm, __shfl_xor_sync(0xffffffffu, tm, 1));
            tm = fmaxf(tm, __shfl_xor_sync(0xffffffffu, tm, 2));
            tm = fmaxf(tm, __shfl_xor_sync(0xffffffffu, tm, 4));
            tm = fmaxf(tm, __shfl_xor_sync(0xffffffffu, tm, 8));
            float mn = fmaxf(m_r[ii], tm);
            float alpha = __expf(m_r[ii] - mn);
            m_r[ii] = mn;
            float p0 = __expf(s0 - mn), p1 = __expf(s1 - mn);
            float p2 = __expf(s2v - mn), p3 = __expf(s3 - mn);
            float rs = p0 + p1 + p2 + p3;
            rs += __shfl_xor_sync(0xffffffffu, rs, 1);
            rs += __shfl_xor_sync(0xffffffffu, rs, 2);
            rs += __shfl_xor_sync(0xffffffffu, rs, 4);
            rs += __shfl_xor_sync(0xffffffffu, rs, 8);
            l_r[ii] = l_r[ii] * alpha + rs;
            u64 ad = dup2(alpha);
            o2[ii][0] = mul2(o2[ii][0], ad);
            o2[ii][1] = mul2(o2[ii][1], ad);
            Ps4[(ty * 4 + ii) * 17 + tx] = make_float4(p0, p1, p2, p3);
        }
        __syncthreads();

        // O += P V (contraction over j)
#pragma unroll
        for (int j4 = 0; j4 < 16; j4++) {
            float4 a4[4];
#pragma unroll
            for (int ii = 0; ii < 4; ii++) a4[ii] = Ps4[(ty * 4 + ii) * 17 + j4];
#pragma unroll
            for (int e = 0; e < 4; e++) {
                float4 bv = Vs4[(j4 * 4 + e) * 16 + tx];
                u64 b01 = pack2(bv.x, bv.y), b23 = pack2(bv.z, bv.w);
#pragma unroll
                for (int ii = 0; ii < 4; ii++) {
                    float av = (e == 0) ? a4[ii].x : (e == 1) ? a4[ii].y : (e == 2) ? a4[ii].z : a4[ii].w;
                    u64 ad = dup2(av);
                    fma2(o2[ii][0], ad, b01);
                    fma2(o2[ii][1], ad, b23);
                }
            }
        }
        __syncthreads();
    }

    float4* ctx4 = (float4*)g_ctx;
#pragma unroll
    for (int ii = 0; ii < 4; ii++) {
        float inv = 1.0f / l_r[ii];
        float2 pa = unpk2(o2[ii][0]);
        float2 pb = unpk2(o2[ii][1]);
        int rg = b * S_ + qt * 64 + ty * 4 + ii;
        ctx4[rg * 16 + tx] = make_float4(pa.x * inv, pa.y * inv, pb.x * inv, pb.y * inv);
    }
}

// ---------------------------------------------------------------------------
// 4) Output projection: out = ctx @ W_eff + bo   ([16384,64] x [64,1024])
//    Block tile 64x128, K=64 single pass, 256 threads, thread tile 8x4.
// ---------------------------------------------------------------------------
__global__ __launch_bounds__(256) void outproj_kernel(float* __restrict__ out,
                                                      const float* __restrict__ bo)
{
    __shared__ float Cs[64 * 64];    // [r][d] natural (16 KB)
    __shared__ float Ws[64 * 128];   // [d][c] natural (32 KB)

    const int tid = threadIdx.x;
    const int ty = tid >> 5;         // 0..7  -> rows ty*8..+7
    const int tx = tid & 31;         // 0..31 -> cols tx*4..+3
    const int r0 = blockIdx.x * 64;
    const int c0 = blockIdx.y * 128;

    float4* Cs4 = (float4*)Cs;
    float4* Ws4 = (float4*)Ws;
    const float4* Cg4 = (const float4*)(g_ctx + r0 * HD);
    const float4* Wg4 = (const float4*)g_weff;

#pragma unroll
    for (int l = 0; l < 4; l++) { int idx4 = tid + l * 256; Cs4[idx4] = Cg4[idx4]; }
#pragma unroll
    for (int l = 0; l < 8; l++) {
        int idx4 = tid + l * 256;               // 64x32 = 2048 float4
        int d = idx4 >> 5, c4 = idx4 & 31;
        Ws4[idx4] = Wg4[d * 256 + (c0 >> 2) + c4];
    }
    __syncthreads();

    u64 acc[8][2];
#pragma unroll
    for (int i = 0; i < 8; i++) { acc[i][0] = 0ull; acc[i][1] = 0ull; }

#pragma unroll
    for (int d4 = 0; d4 < 16; d4++) {
        float4 a4[8];
#pragma unroll
        for (int i = 0; i < 8; i++) a4[i] = Cs4[(ty * 8 + i) * 16 + d4];
#pragma unroll
        for (int e = 0; e < 4; e++) {
            float4 bw = Ws4[(d4 * 4 + e) * 32 + tx];
            u64 b01 = pack2(bw.x, bw.y), b23 = pack2(bw.z, bw.w);
#pragma unroll
            for (int i = 0; i < 8; i++) {
                float av = (e == 0) ? a4[i].x : (e == 1) ? a4[i].y : (e == 2) ? a4[i].z : a4[i].w;
                u64 ad = dup2(av);
                fma2(acc[i][0], ad, b01);
                fma2(acc[i][1], ad, b23);
            }
        }
    }

    const float4 bb = ((const float4*)bo)[(c0 >> 2) + tx];
    float4* out4 = (float4*)out;
#pragma unroll
    for (int i = 0; i < 8; i++) {
        float2 p0 = unpk2(acc[i][0]);
        float2 p1 = unpk2(acc[i][1]);
        out4[(r0 + ty * 8 + i) * 256 + (c0 >> 2) + tx] =
            make_float4(p0.x + bb.x, p0.y + bb.y, p1.x + bb.z, p1.y + bb.w);
    }
}

// ---------------------------------------------------------------------------
extern "C" void kernel_launch(void* const* d_in, const int* in_sizes, int n_in,
                              void* d_out, int out_size)
{
    (void)in_sizes; (void)n_in; (void)out_size;
    const float* query = (const float*)d_in[0];
    const float* key_  = (const float*)d_in[1];
    const float* value = (const float*)d_in[2];
    const float* Wq    = (const float*)d_in[3];
    const float* bq    = (const float*)d_in[4];
    const float* Wk    = (const float*)d_in[5];
    const float* bk    = (const float*)d_in[6];
    const float* Wv    = (const float*)d_in[7];
    const float* bv    = (const float*)d_in[8];
    const float* Wo    = (const float*)d_in[9];
    const float* bo    = (const float*)d_in[10];

    cudaFuncSetAttribute(attn_kernel, cudaFuncAttributeMaxDynamicSharedMemorySize,
                         ATTN_SMEM_BYTES);

    qkv_proj_kernel<<<dim3(128, 1, 3), 256>>>(query, key_, value, Wq, Wk, Wv, bq, bk, bv);
    weff_kernel<<<256, 256>>>(Wo);
    attn_kernel<<<dim3(32, 8), 256, ATTN_SMEM_BYTES>>>();
    outproj_kernel<<<dim3(256, 8), 256>>>((float*)d_out, bo);
}

// round 6
// speedup vs baseline: 1.1635x; 1.1635x over previous
#include <cuda_runtime.h>

// MultiHeadAttention_45732811768295 — fp32 FFMA2 (f32x2) pipeline, round 3.
//   1) qkv_proj_kernel : q/k/v = X @ W + b        (3x [16384,1024]x[1024,64])
//                        64x64 tiles, double-buffered smem, reg prefetch, 1 sync/iter
//   2) weff_kernel     : W_eff[d,m] = sum_h Wo[h*64+d, m]
//   3) attn_kernel     : flash softmax(QK^T/8)V, 32-row q tiles, 512 blocks
//   4) outproj_kernel  : out = ctx @ W_eff + bo, 64x256 tiles, 8x8 thread tile

#define B_  8
#define S_  2048
#define DM  1024
#define HD  64
#define ROWS_TOT (B_ * S_)   // 16384

typedef unsigned long long u64;

__device__ __forceinline__ u64 pack2(float x, float y) {
    u64 r; asm("mov.b64 %0, {%1,%2};" : "=l"(r) : "f"(x), "f"(y)); return r;
}
__device__ __forceinline__ u64 dup2(float x) { return pack2(x, x); }
__device__ __forceinline__ void fma2(u64 &d, u64 a, u64 b) {
    asm("fma.rn.f32x2 %0, %1, %2, %0;" : "+l"(d) : "l"(a), "l"(b));
}
__device__ __forceinline__ u64 mul2(u64 a, u64 b) {
    u64 d; asm("mul.rn.f32x2 %0, %1, %2;" : "=l"(d) : "l"(a), "l"(b)); return d;
}
__device__ __forceinline__ float2 unpk2(u64 v) {
    float2 f; asm("mov.b64 {%0,%1}, %2;" : "=f"(f.x), "=f"(f.y) : "l"(v)); return f;
}

// Scratch (device globals; runtime allocation forbidden)
__device__ float g_q[ROWS_TOT * HD];
__device__ float g_k[ROWS_TOT * HD];
__device__ float g_v[ROWS_TOT * HD];
__device__ float g_ctx[ROWS_TOT * HD];
__device__ float g_weff[HD * DM];

// ---------------------------------------------------------------------------
// 1) QKV projection.  Block tile 64x64, Ktile=32, 256 threads, thread 4x4.
//    Double-buffered smem + register prefetch: one __syncthreads per k-iter,
//    LDG latency fully overlapped with compute.
// ---------------------------------------------------------------------------
#define QKV_APAD 9   // float4 per A row (36 floats) — kills 2-row broadcast conflict

__global__ __launch_bounds__(256, 3) void qkv_proj_kernel(
    const float* __restrict__ in_q, const float* __restrict__ in_k, const float* __restrict__ in_v,
    const float* __restrict__ Wq, const float* __restrict__ Wk, const float* __restrict__ Wv,
    const float* __restrict__ bq, const float* __restrict__ bk, const float* __restrict__ bv)
{
    __shared__ float As[2][64 * (QKV_APAD * 4)];  // [r][k], padded rows
    __shared__ float Bs[2][32 * 64];              // [k][c] natural

    const float* X; const float* W; const float* bias; float* out;
    if (blockIdx.z == 0)      { X = in_q; W = Wq; bias = bq; out = g_q; }
    else if (blockIdx.z == 1) { X = in_k; W = Wk; bias = bk; out = g_k; }
    else                      { X = in_v; W = Wv; bias = bv; out = g_v; }

    const int tid = threadIdx.x;
    const int ty  = tid >> 4;      // 0..15 -> rows ty*4..+3
    const int tx  = tid & 15;      // 0..15 -> cols tx*4..+3
    const int rowBase = blockIdx.x * 64;

    const float4* X4 = (const float4*)X;
    const float4* W4 = (const float4*)W;

    // per-thread load coordinates (2 float4 for A, 2 for B)
    const int aR0 = tid >> 3,            aK0 = tid & 7;          // l=0
    const int aR1 = (tid + 256) >> 3,    aK1 = (tid + 256) & 7;  // l=1
    const int bK0 = tid >> 4,            bC0 = tid & 15;
    const int bK1 = (tid + 256) >> 4,    bC1 = (tid + 256) & 15;

    // prologue: tile 0 straight into buffer 0
    {
        float4* A4 = (float4*)As[0];
        float4* Bb4 = (float4*)Bs[0];
        A4[aR0 * QKV_APAD + aK0] = X4[(rowBase + aR0) * 256 + aK0];
        A4[aR1 * QKV_APAD + aK1] = X4[(rowBase + aR1) * 256 + aK1];
        Bb4[bK0 * 16 + bC0] = W4[bK0 * 16 + bC0];
        Bb4[bK1 * 16 + bC1] = W4[bK1 * 16 + bC1];
    }

    u64 acc[4][2];
#pragma unroll
    for (int i = 0; i < 4; i++) { acc[i][0] = 0ull; acc[i][1] = 0ull; }

    for (int kt = 0; kt < 32; kt++) {
        const int buf = kt & 1;
        __syncthreads();   // previous iter's stores to `buf` visible

        float4 ar0, ar1, br0, br1;
        if (kt + 1 < 32) {
            const int k4b = (kt + 1) * 8;
            const int kb  = (kt + 1) * 32;
            ar0 = X4[(rowBase + aR0) * 256 + k4b + aK0];
            ar1 = X4[(rowBase + aR1) * 256 + k4b + aK1];
            br0 = W4[(kb + bK0) * 16 + bC0];
            br1 = W4[(kb + bK1) * 16 + bC1];
        }

        const float4* A4 = (const float4*)As[buf];
        const float4* Bb4 = (const float4*)Bs[buf];
#pragma unroll
        for (int k4 = 0; k4 < 8; k4++) {
            float4 a4[4];
#pragma unroll
            for (int i = 0; i < 4; i++) a4[i] = A4[(ty * 4 + i) * QKV_APAD + k4];
#pragma unroll
            for (int e = 0; e < 4; e++) {
                float4 b = Bb4[(k4 * 4 + e) * 16 + tx];
                u64 b01 = pack2(b.x, b.y), b23 = pack2(b.z, b.w);
#pragma unroll
                for (int i = 0; i < 4; i++) {
                    float av = (e == 0) ? a4[i].x : (e == 1) ? a4[i].y : (e == 2) ? a4[i].z : a4[i].w;
                    u64 ad = dup2(av);
                    fma2(acc[i][0], ad, b01);
                    fma2(acc[i][1], ad, b23);
                }
            }
        }

        if (kt + 1 < 32) {
            float4* An4 = (float4*)As[buf ^ 1];
            float4* Bn4 = (float4*)Bs[buf ^ 1];
            An4[aR0 * QKV_APAD + aK0] = ar0;
            An4[aR1 * QKV_APAD + aK1] = ar1;
            Bn4[bK0 * 16 + bC0] = br0;
            Bn4[bK1 * 16 + bC1] = br1;
        }
    }

    const float4 bb = ((const float4*)bias)[tx];
    float4* out4 = (float4*)out;
#pragma unroll
    for (int i = 0; i < 4; i++) {
        float2 p0 = unpk2(acc[i][0]);
        float2 p1 = unpk2(acc[i][1]);
        out4[(rowBase + ty * 4 + i) * 16 + tx] =
            make_float4(p0.x + bb.x, p0.y + bb.y, p1.x + bb.z, p1.y + bb.w);
    }
}

// ---------------------------------------------------------------------------
// 2) W_eff[d,m] = sum_h Wo[h*64+d, m]
// ---------------------------------------------------------------------------
__global__ void weff_kernel(const float* __restrict__ Wo)
{
    int idx = blockIdx.x * 256 + threadIdx.x;     // 64*1024
    int d = idx >> 10, m = idx & 1023;
    float s = 0.f;
#pragma unroll
    for (int h = 0; h < 16; h++) s += Wo[(h * 64 + d) * 1024 + m];
    g_weff[idx] = s;
    (void)d; (void)m;
}

// ---------------------------------------------------------------------------
// 3) Attention: 32-row q tiles (grid 64x8 = 512 blocks), 64-key tiles,
//    256 threads, thread tile 2 rows x 4 cols, occ-3 latency hiding.
// ---------------------------------------------------------------------------
#define ATTN_SMEM_FLOATS (32*68 + 64*68 + 64*64 + 32*68)
#define ATTN_SMEM_BYTES  (ATTN_SMEM_FLOATS * 4)   // 51200

__global__ __launch_bounds__(256, 3) void attn_kernel()
{
    extern __shared__ float sm[];
    float* Qs = sm;                 // [i][d]  32x68 padded
    float* Ks = Qs + 32 * 68;       // [d][j]  64x68 transposed padded
    float* Vs = Ks + 64 * 68;       // [j][d]  64x64 natural
    float* Ps = Vs + 64 * 64;       // [i][j]  32x68 padded

    const int b  = blockIdx.y;
    const int qt = blockIdx.x;
    const int tid = threadIdx.x;
    const int ty = tid >> 4;        // 0..15 -> rows ty*2..+1
    const int tx = tid & 15;        // cols tx*4..+3

    const float4* Qg4 = (const float4*)(g_q + (b * S_ + qt * 32) * HD);
    const float*  Kg  = g_k + b * S_ * HD;
    const float*  Vg  = g_v + b * S_ * HD;

    float4* Qs4 = (float4*)Qs;      // row stride 17
    float4* Ks4 = (float4*)Ks;      // row stride 17
    float4* Vs4 = (float4*)Vs;      // row stride 16
    float4* Ps4 = (float4*)Ps;      // row stride 17

    // Q tile: 512 float4
#pragma unroll
    for (int l = 0; l < 2; l++) {
        int idx4 = tid + l * 256;
        int r = idx4 >> 4, d4 = idx4 & 15;
        Qs4[r * 17 + d4] = Qg4[idx4];
    }

    float m_r[2], l_r[2];
    u64 o2[2][2];
#pragma unroll
    for (int ii = 0; ii < 2; ii++) { m_r[ii] = -1e30f; l_r[ii] = 0.f; o2[ii][0] = 0ull; o2[ii][1] = 0ull; }

    for (int kt = 0; kt < 32; kt++) {
        const float4* Kt4 = (const float4*)(Kg + kt * 64 * HD);
        const float4* Vt4 = (const float4*)(Vg + kt * 64 * HD);
#pragma unroll
        for (int l = 0; l < 4; l++) {
            int idx4 = tid + l * 256;           // 0..1023
            int d4 = idx4 >> 6, j = idx4 & 63;  // j consecutive -> conflict-free STS, L1-friendly LDG
            float4 v = Kt4[j * 16 + d4];
            int d = d4 * 4;
            Ks[(d + 0) * 68 + j] = v.x;
            Ks[(d + 1) * 68 + j] = v.y;
            Ks[(d + 2) * 68 + j] = v.z;
            Ks[(d + 3) * 68 + j] = v.w;
            Vs4[idx4] = Vt4[idx4];
        }
        __syncthreads();

        // S = Q K^T over d
        u64 s2[2][2];
#pragma unroll
        for (int ii = 0; ii < 2; ii++) { s2[ii][0] = 0ull; s2[ii][1] = 0ull; }

#pragma unroll
        for (int d4 = 0; d4 < 16; d4++) {
            float4 a4[2];
#pragma unroll
            for (int ii = 0; ii < 2; ii++) a4[ii] = Qs4[(ty * 2 + ii) * 17 + d4];
#pragma unroll
            for (int e = 0; e < 4; e++) {
                float4 bk = Ks4[(d4 * 4 + e) * 17 + tx];
                u64 b01 = pack2(bk.x, bk.y), b23 = pack2(bk.z, bk.w);
#pragma unroll
                for (int ii = 0; ii < 2; ii++) {
                    float av = (e == 0) ? a4[ii].x : (e == 1) ? a4[ii].y : (e == 2) ? a4[ii].z : a4[ii].w;
                    u64 ad = dup2(av);
                    fma2(s2[ii][0], ad, b01);
                    fma2(s2[ii][1], ad, b23);
                }
            }
        }

        // Online softmax (row reductions over the 16 tx lanes)
#pragma unroll
        for (int ii = 0; ii < 2; ii++) {
            float2 sa = unpk2(s2[ii][0]);
            float2 sb = unpk2(s2[ii][1]);
            float s0 = sa.x * 0.125f, s1 = sa.y * 0.125f, s2v = sb.x * 0.125f, s3 = sb.y * 0.125f;
            float tm = fmaxf(fmaxf(s0, s1), fmaxf(s2v, s3));
            tm = fmaxf(tm, __shfl_xor_sync(0xffffffffu, tm, 1));
            tm = fmaxf(tm, __shfl_xor_sync(0xffffffffu, tm, 2));
            tm = fmaxf(tm, __shfl_xor_sync(0xffffffffu, tm, 4));
            tm = fmaxf(tm, __shfl_xor_sync(0xffffffffu, tm, 8));
            float mn = fmaxf(m_r[ii], tm);
            float alpha = __expf(m_r[ii] - mn);
            m_r[ii] = mn;
            float p0 = __expf(s0 - mn), p1 = __expf(s1 - mn);
            float p2 = __expf(s2v - mn), p3 = __expf(s3 - mn);
            float rs = p0 + p1 + p2 + p3;
            rs += __shfl_xor_sync(0xffffffffu, rs, 1);
            rs += __shfl_xor_sync(0xffffffffu, rs, 2);
            rs += __shfl_xor_sync(0xffffffffu, rs, 4);
            rs += __shfl_xor_sync(0xffffffffu, rs, 8);
            l_r[ii] = l_r[ii] * alpha + rs;
            u64 ad = dup2(alpha);
            o2[ii][0] = mul2(o2[ii][0], ad);
            o2[ii][1] = mul2(o2[ii][1], ad);
            Ps4[(ty * 2 + ii) * 17 + tx] = make_float4(p0, p1, p2, p3);
        }
        __syncthreads();

        // O += P V over j
#pragma unroll
        for (int j4 = 0; j4 < 16; j4++) {
            float4 a4[2];
#pragma unroll
            for (int ii = 0; ii < 2; ii++) a4[ii] = Ps4[(ty * 2 + ii) * 17 + j4];
#pragma unroll
            for (int e = 0; e < 4; e++) {
                float4 bv = Vs4[(j4 * 4 + e) * 16 + tx];
                u64 b01 = pack2(bv.x, bv.y), b23 = pack2(bv.z, bv.w);
#pragma unroll
                for (int ii = 0; ii < 2; ii++) {
                    float av = (e == 0) ? a4[ii].x : (e == 1) ? a4[ii].y : (e == 2) ? a4[ii].z : a4[ii].w;
                    u64 ad = dup2(av);
                    fma2(o2[ii][0], ad, b01);
                    fma2(o2[ii][1], ad, b23);
                }
            }
        }
        __syncthreads();   // Ks/Vs/Ps free for next iter
    }

    float4* ctx4 = (float4*)g_ctx;
#pragma unroll
    for (int ii = 0; ii < 2; ii++) {
        float inv = 1.0f / l_r[ii];
        float2 pa = unpk2(o2[ii][0]);
        float2 pb = unpk2(o2[ii][1]);
        int rg = b * S_ + qt * 32 + ty * 2 + ii;
        ctx4[rg * 16 + tx] = make_float4(pa.x * inv, pa.y * inv, pb.x * inv, pb.y * inv);
    }
}

// ---------------------------------------------------------------------------
// 4) Output projection: out = ctx @ W_eff + bo.
//    Block tile 64x256, K=64 single pass, 256 threads, thread tile 8x8
//    (split columns: tx and tx+32 float4 groups -> conflict-free LDS.128).
// ---------------------------------------------------------------------------
#define OUTPROJ_SMEM_BYTES ((64*64 + 64*256) * 4)   // 81920

__global__ __launch_bounds__(256, 2) void outproj_kernel(float* __restrict__ out,
                                                         const float* __restrict__ bo)
{
    extern __shared__ float smo[];
    float* Cs = smo;                // [r][d] 64x64 natural (16 KB)
    float* Ws = smo + 64 * 64;      // [d][c] 64x256 natural (64 KB)

    const int tid = threadIdx.x;
    const int ty = tid >> 5;        // 0..7  -> rows ty*8..+7 (warp = one row group)
    const int tx = tid & 31;        // cols: {tx*4..+3} and {128+tx*4..+3}
    const int r0 = blockIdx.x * 64;
    const int c4base = blockIdx.y * 64;   // col/4 base

    float4* Cs4 = (float4*)Cs;
    float4* Ws4 = (float4*)Ws;
    const float4* Cg4 = (const float4*)(g_ctx + r0 * HD);
    const float4* Wg4 = (const float4*)g_weff;

#pragma unroll
    for (int l = 0; l < 4; l++) { int idx4 = tid + l * 256; Cs4[idx4] = Cg4[idx4]; }
#pragma unroll
    for (int l = 0; l < 16; l++) {
        int idx4 = tid + l * 256;              // 64x64 float4 = 4096
        int d = idx4 >> 6, c4 = idx4 & 63;
        Ws4[idx4] = Wg4[d * 256 + c4base + c4];
    }
    __syncthreads();

    u64 acc[8][4];
#pragma unroll
    for (int i = 0; i < 8; i++)
#pragma unroll
        for (int p = 0; p < 4; p++) acc[i][p] = 0ull;

#pragma unroll
    for (int d4 = 0; d4 < 16; d4++) {
        float4 a4[8];
#pragma unroll
        for (int i = 0; i < 8; i++) a4[i] = Cs4[(ty * 8 + i) * 16 + d4];
#pragma unroll
        for (int e = 0; e < 4; e++) {
            float4 b0 = Ws4[(d4 * 4 + e) * 64 + tx];
            float4 b1 = Ws4[(d4 * 4 + e) * 64 + 32 + tx];
            u64 b00 = pack2(b0.x, b0.y), b01 = pack2(b0.z, b0.w);
            u64 b10 = pack2(b1.x, b1.y), b11 = pack2(b1.z, b1.w);
#pragma unroll
            for (int i = 0; i < 8; i++) {
                float av = (e == 0) ? a4[i].x : (e == 1) ? a4[i].y : (e == 2) ? a4[i].z : a4[i].w;
                u64 ad = dup2(av);
                fma2(acc[i][0], ad, b00);
                fma2(acc[i][1], ad, b01);
                fma2(acc[i][2], ad, b10);
                fma2(acc[i][3], ad, b11);
            }
        }
    }

    const float4 bb0 = ((const float4*)bo)[c4base + tx];
    const float4 bb1 = ((const float4*)bo)[c4base + 32 + tx];
    float4* out4 = (float4*)out;
#pragma unroll
    for (int i = 0; i < 8; i++) {
        float2 q0 = unpk2(acc[i][0]);
        float2 q1 = unpk2(acc[i][1]);
        float2 q2 = unpk2(acc[i][2]);
        float2 q3 = unpk2(acc[i][3]);
        int row = r0 + ty * 8 + i;
        out4[row * 256 + c4base + tx] =
            make_float4(q0.x + bb0.x, q0.y + bb0.y, q1.x + bb0.z, q1.y + bb0.w);
        out4[row * 256 + c4base + 32 + tx] =
            make_float4(q2.x + bb1.x, q2.y + bb1.y, q3.x + bb1.z, q3.y + bb1.w);
    }
}

// ---------------------------------------------------------------------------
extern "C" void kernel_launch(void* const* d_in, const int* in_sizes, int n_in,
                              void* d_out, int out_size)
{
    (void)in_sizes; (void)n_in; (void)out_size;
    const float* query = (const float*)d_in[0];
    const float* key_  = (const float*)d_in[1];
    const float* value = (const float*)d_in[2];
    const float* Wq    = (const float*)d_in[3];
    const float* bq    = (const float*)d_in[4];
    const float* Wk    = (const float*)d_in[5];
    const float* bk    = (const float*)d_in[6];
    const float* Wv    = (const float*)d_in[7];
    const float* bv    = (const float*)d_in[8];
    const float* Wo    = (const float*)d_in[9];
    const float* bo    = (const float*)d_in[10];

    cudaFuncSetAttribute(attn_kernel, cudaFuncAttributeMaxDynamicSharedMemorySize,
                         ATTN_SMEM_BYTES);
    cudaFuncSetAttribute(outproj_kernel, cudaFuncAttributeMaxDynamicSharedMemorySize,
                         OUTPROJ_SMEM_BYTES);

    qkv_proj_kernel<<<dim3(256, 1, 3), 256>>>(query, key_, value, Wq, Wk, Wv, bq, bk, bv);
    weff_kernel<<<256, 256>>>(Wo);
    attn_kernel<<<dim3(64, 8), 256, ATTN_SMEM_BYTES>>>();
    outproj_kernel<<<dim3(256, 4), 256, OUTPROJ_SMEM_BYTES>>>((float*)d_out, bo);
}